// round 8
// baseline (speedup 1.0000x reference)
#include <cuda_runtime.h>
#include <cstdint>

// Problem constants:
//   features: [B=4, C=256, H=64, W=64] fp32
//   rois:     [R=2048, 5] (batch, x1, y1, x2, y2), SPATIAL_SCALE = 0.25
//   Grid positions h=w={0,7,...,63} are EXACT integers -> bilinear == gather.
//   output:   [R, C, 9, 9] fp32  (maxpool 2x2 s1 of region-of-discard-masked 10x10)

#define BATCH 4
#define NCH   256
#define NPOS  100        // 10x10 grid per channel
#define CHB   32         // channels per block (chunk)
#define NCHUNK (NCH / CHB)          // 8
#define THREADS 256                 // 2 rois x 4 strips x 32 channels
#define ROIS_PER_BLOCK 16
#define GPITCH 101                  // padded pos pitch (gcd(101,32)=1 -> no conflicts)
#define BUFSZ (CHB * 81)            // 2592 floats = 10368 B staging per roi

// Transposed gather: G_t[b][pos][c] = features[b,c,7i,7j], channels contiguous.
__device__ float g_Gt[BATCH * NPOS * NCH];

__global__ void gather_grid_kernel(const float* __restrict__ feat) {
    int idx = blockIdx.x * blockDim.x + threadIdx.x;   // b*100*256 + p*256 + c
    if (idx >= BATCH * NPOS * NCH) return;
    int c  = idx % NCH;
    int bp = idx / NCH;
    int p  = bp % NPOS;
    int b  = bp / NPOS;
    int i = p / 10;
    int j = p % 10;
    g_Gt[idx] = feat[(((b * NCH + c) * 64) + i * 7) * 64 + j * 7];
}

// One column-strip of NCOLS grid columns -> NCOLS-1 output columns, reading
// this channel's grid row from SMEM (pos stride 1). Masked points skip the
// LDS (warp-uniform predicate) and contribute 0, matching the reference.
template<int NCOLS>
__device__ __forceinline__ void strip(const float* __restrict__ gt,
                                      float* __restrict__ so,
                                      float x1, float x2, float y1, float y2,
                                      int c0)
{
    bool inw[NCOLS];
    #pragma unroll
    for (int k = 0; k < NCOLS; k++) {
        float w = (float)(c0 + k) * 7.0f;
        inw[k] = (w >= x1) && (w <= x2);
    }

    float prev[NCOLS], cur[NCOLS];
    {
        bool inh0 = (0.0f >= y1) && (0.0f <= y2);
        #pragma unroll
        for (int k = 0; k < NCOLS; k++) {
            float v = 0.0f;
            if (!(inh0 && inw[k])) v = gt[c0 + k];
            prev[k] = v;
        }
    }
    #pragma unroll
    for (int i = 1; i < 10; i++) {
        float h = (float)i * 7.0f;
        bool inh = (h >= y1) && (h <= y2);
        #pragma unroll
        for (int k = 0; k < NCOLS; k++) {
            float v = 0.0f;
            if (!(inh && inw[k])) v = gt[i * 10 + c0 + k];
            cur[k] = v;
        }
        float vm[NCOLS];
        #pragma unroll
        for (int k = 0; k < NCOLS; k++)
            vm[k] = fmaxf(prev[k], cur[k]);
        #pragma unroll
        for (int k = 0; k < NCOLS - 1; k++)
            so[(i - 1) * 9 + k] = fmaxf(vm[k], vm[k + 1]);
        #pragma unroll
        for (int k = 0; k < NCOLS; k++)
            prev[k] = cur[k];
    }
}

__global__ __launch_bounds__(THREADS) void rod_align_max_kernel(
    const float* __restrict__ rois,
    float* __restrict__ out)
{
    extern __shared__ __align__(16) float smem[];
    float* sG   = smem;                          // [4][CHB][GPITCH] = 51712 B
    float* sbuf = smem + BATCH * CHB * GPITCH;   // 4 x BUFSZ = 41472 B

    const int chunk = blockIdx.x;                // channel chunk (0..7)
    const int roi0  = blockIdx.y * ROIS_PER_BLOCK;
    const int tid   = threadIdx.x;
    const int c     = tid & (CHB - 1);           // channel (lane)
    const int q     = (tid >> 5) & 3;            // column strip
    const int g     = tid >> 7;                  // which roi of the pair

    // ---- One-time: load this chunk's G slice for ALL batches into smem. ----
    // Each warp loads (b,pos) entries; lanes = 32 consecutive channels (128B LDG).
    {
        const int warp = tid >> 5;
        const int lane = tid & 31;
        for (int idx = warp; idx < BATCH * NPOS; idx += 8) {
            int b = idx / NPOS;
            int p = idx - b * NPOS;
            float v = g_Gt[(b * NPOS + p) * NCH + chunk * CHB + lane];
            sG[(b * CHB + lane) * GPITCH + p] = v;
        }
    }
    __syncthreads();

    const int jstart[4] = {0, 3, 5, 7};   // output col start per strip
    const int ncols[4]  = {4, 3, 3, 3};   // grid cols per strip
    (void)ncols;

    // ---- ROI loop: 8 pairs, double-buffered pairs of staging buffers. ----
    for (int t = 0; t < ROIS_PER_BLOCK; t += 2) {
        const int parity = (t >> 1) & 1;
        float* buf = sbuf + (parity * 2 + g) * BUFSZ;

        // Ensure the TMA that last read this buffer pair has drained.
        if (tid == 0)
            asm volatile("cp.async.bulk.wait_group.read 1;" ::: "memory");
        __syncthreads();

        const int r = roi0 + t + g;
        const float x1 = rois[r * 5 + 1] * 0.25f;
        const float y1 = rois[r * 5 + 2] * 0.25f;
        const float x2 = rois[r * 5 + 3] * 0.25f;
        const float y2 = rois[r * 5 + 4] * 0.25f;
        const int   b  = (int)rois[r * 5 + 0];

        const float* gt = sG + (b * CHB + c) * GPITCH;
        float* so = buf + c * 81 + jstart[q];

        if (q == 0)      strip<4>(gt, so, x1, x2, y1, y2, 0);
        else if (q == 1) strip<3>(gt, so, x1, x2, y1, y2, 3);
        else if (q == 2) strip<3>(gt, so, x1, x2, y1, y2, 5);
        else             strip<3>(gt, so, x1, x2, y1, y2, 7);

        asm volatile("fence.proxy.async.shared::cta;" ::: "memory");
        __syncthreads();

        if (tid == 0) {
            #pragma unroll
            for (int gg = 0; gg < 2; gg++) {
                uint32_t saddr;
                const float* src = sbuf + (parity * 2 + gg) * BUFSZ;
                asm("{ .reg .u64 t; cvta.to.shared.u64 t, %1; cvt.u32.u64 %0, t; }"
                    : "=r"(saddr) : "l"(src));
                float* gdst = out + (size_t)((roi0 + t + gg) * NCH + chunk * CHB) * 81;
                asm volatile(
                    "cp.async.bulk.global.shared::cta.bulk_group [%0], [%1], %2;"
                    :: "l"(gdst), "r"(saddr), "r"((int)(BUFSZ * 4)) : "memory");
            }
            asm volatile("cp.async.bulk.commit_group;" ::: "memory");
        }
    }

    // Do not exit while TMA is still reading this CTA's smem.
    if (tid == 0)
        asm volatile("cp.async.bulk.wait_group.read 0;" ::: "memory");
}

extern "C" void kernel_launch(void* const* d_in, const int* in_sizes, int n_in,
                              void* d_out, int out_size) {
    const float* features = (const float*)d_in[0];   // [4,256,64,64]
    const float* rois     = (const float*)d_in[1];   // [2048,5]
    float* out = (float*)d_out;                      // [2048,256,9,9]

    const int R = in_sizes[1] / 5;                   // 2048

    int n_g = BATCH * NPOS * NCH;
    gather_grid_kernel<<<(n_g + 255) / 256, 256>>>(features);

    const int smem_bytes = (BATCH * CHB * GPITCH + 4 * BUFSZ) * 4;  // 93184 B
    cudaFuncSetAttribute(rod_align_max_kernel,
                         cudaFuncAttributeMaxDynamicSharedMemorySize, smem_bytes);

    dim3 grid(NCHUNK, R / ROIS_PER_BLOCK);           // (8, 128)
    rod_align_max_kernel<<<grid, THREADS, smem_bytes>>>(rois, out);
}

// round 9
// speedup vs baseline: 1.3450x; 1.3450x over previous
#include <cuda_runtime.h>
#include <cstdint>

// Problem constants:
//   features: [B=4, C=256, H=64, W=64] fp32
//   rois:     [R=2048, 5] (batch, x1, y1, x2, y2), SPATIAL_SCALE = 0.25
//   Grid positions h=w={0,7,...,63} are EXACT integers -> bilinear == gather.
//   output:   [R, C, 9, 9] fp32  (maxpool 2x2 s1 of region-of-discard-masked 10x10)

#define BATCH 4
#define NCH   256
#define NPOS  100        // 10x10 grid per channel
#define CHB   64         // channels per block
#define NCHUNK (NCH / CHB)
#define THREADS 256      // 64 channels x 4 column-strips

// Transposed gather: G_t[b][pos][c] = features[b,c,7i,7j], channels contiguous.
__device__ float g_Gt[BATCH * NPOS * NCH];

__global__ void gather_grid_kernel(const float* __restrict__ feat) {
    int idx = blockIdx.x * blockDim.x + threadIdx.x;   // b*100*256 + p*256 + c
    if (idx >= BATCH * NPOS * NCH) return;
    int c  = idx % NCH;
    int bp = idx / NCH;
    int p  = bp % NPOS;
    int b  = bp / NPOS;
    int i = p / 10;
    int j = p % 10;
    g_Gt[idx] = feat[(((b * NCH + c) * 64) + i * 7) * 64 + j * 7];
}

// One column-strip of NCOLS grid columns -> NCOLS-1 output columns.
// ALL 10*NCOLS loads are issued up front (independent, predicated) so the
// thread has ~30-40 loads in flight (MLP-bound, not latency-bound); the
// max/store phase then runs on register data only.
template<int NCOLS>
__device__ __forceinline__ void strip(const float* __restrict__ gt,
                                      float* __restrict__ so,
                                      float x1, float x2, float y1, float y2,
                                      int c0)
{
    bool inw[NCOLS];
    #pragma unroll
    for (int k = 0; k < NCOLS; k++) {
        float w = (float)(c0 + k) * 7.0f;
        inw[k] = (w >= x1) && (w <= x2);
    }

    // Phase 1: front-batched predicated loads of the whole 10-row window.
    float v[10][NCOLS];
    #pragma unroll
    for (int i = 0; i < 10; i++) {
        float h = (float)i * 7.0f;
        bool inh = (h >= y1) && (h <= y2);
        #pragma unroll
        for (int k = 0; k < NCOLS; k++) {
            float val = 0.0f;
            if (!(inh && inw[k])) val = __ldg(&gt[(i * 10 + k) * NCH]);
            v[i][k] = val;
        }
    }

    // Phase 2: 2x2 max over registers, store 9 output rows.
    #pragma unroll
    for (int i = 0; i < 9; i++) {
        float vm[NCOLS];
        #pragma unroll
        for (int k = 0; k < NCOLS; k++)
            vm[k] = fmaxf(v[i][k], v[i + 1][k]);
        #pragma unroll
        for (int k = 0; k < NCOLS - 1; k++)
            so[i * 9 + k] = fmaxf(vm[k], vm[k + 1]);
    }
}

__global__ __launch_bounds__(THREADS, 4) void rod_align_max_kernel(
    const float* __restrict__ rois,
    float* __restrict__ out)
{
    __shared__ __align__(16) float sout[CHB * 81];   // 20736 B staged outputs

    const int r     = blockIdx.x;      // roi
    const int chunk = blockIdx.y;      // channel chunk
    const int tid   = threadIdx.x;
    // 4 column-strips; within each strip, warps hold 32 consecutive channels.
    //   q=0: cols 0..3 -> j=0..2     q=1: cols 3..5 -> j=3..4
    //   q=2: cols 5..7 -> j=5..6     q=3: cols 7..9 -> j=7..8
    const int c = tid & (CHB - 1);     // channel within chunk
    const int q = tid >> 6;            // strip id

    const float x1 = rois[r * 5 + 1] * 0.25f;
    const float y1 = rois[r * 5 + 2] * 0.25f;
    const float x2 = rois[r * 5 + 3] * 0.25f;
    const float y2 = rois[r * 5 + 4] * 0.25f;
    const int   b  = (int)rois[r * 5 + 0];

    const float* gbase = g_Gt + b * (NPOS * NCH) + chunk * CHB + c;
    float* so = sout + c * 81;

    if (q == 0)      strip<4>(gbase,           so,     x1, x2, y1, y2, 0);
    else if (q == 1) strip<3>(gbase + 3 * NCH, so + 3, x1, x2, y1, y2, 3);
    else if (q == 2) strip<3>(gbase + 5 * NCH, so + 5, x1, x2, y1, y2, 5);
    else             strip<3>(gbase + 7 * NCH, so + 7, x1, x2, y1, y2, 7);

    // Hand the 20736B contiguous staged block to TMA for the global write.
    asm volatile("fence.proxy.async.shared::cta;" ::: "memory");
    __syncthreads();
    if (tid == 0) {
        uint32_t saddr;
        asm("{ .reg .u64 t; cvta.to.shared.u64 t, %1; cvt.u32.u64 %0, t; }"
            : "=r"(saddr) : "l"(sout));
        float* gdst = out + (size_t)(r * NCH + chunk * CHB) * 81;
        asm volatile(
            "cp.async.bulk.global.shared::cta.bulk_group [%0], [%1], %2;"
            :: "l"(gdst), "r"(saddr), "r"((int)(CHB * 81 * 4)) : "memory");
        asm volatile("cp.async.bulk.commit_group;" ::: "memory");
        // Must not exit the CTA while TMA is still reading our smem.
        asm volatile("cp.async.bulk.wait_group.read 0;" ::: "memory");
    }
}

extern "C" void kernel_launch(void* const* d_in, const int* in_sizes, int n_in,
                              void* d_out, int out_size) {
    const float* features = (const float*)d_in[0];   // [4,256,64,64]
    const float* rois     = (const float*)d_in[1];   // [2048,5]
    float* out = (float*)d_out;                      // [2048,256,9,9]

    const int R = in_sizes[1] / 5;                   // 2048

    int n_g = BATCH * NPOS * NCH;
    gather_grid_kernel<<<(n_g + 255) / 256, 256>>>(features);

    dim3 grid(R, NCHUNK);
    rod_align_max_kernel<<<grid, THREADS>>>(rois, out);
}

// round 10
// speedup vs baseline: 1.4230x; 1.0580x over previous
#include <cuda_runtime.h>
#include <cstdint>

// Problem constants:
//   features: [B=4, C=256, H=64, W=64] fp32
//   rois:     [R=2048, 5] (batch, x1, y1, x2, y2), SPATIAL_SCALE = 0.25
//   Grid positions h=w={0,7,...,63} are EXACT integers -> bilinear == gather.
//   output:   [R, C, 9, 9] fp32  (maxpool 2x2 s1 of region-of-discard-masked 10x10)

#define BATCH 4
#define NCH   256
#define NPOS  100        // 10x10 grid per channel
#define CHB   64         // channels per block
#define NCHUNK (NCH / CHB)
#define THREADS 256      // 64 channels x 4 column-strips

// Transposed gather: G_t[b][pos][c] = features[b,c,7i,7j], channels contiguous.
__device__ float g_Gt[BATCH * NPOS * NCH];

__global__ void gather_grid_kernel(const float* __restrict__ feat) {
    int idx = blockIdx.x * blockDim.x + threadIdx.x;   // b*100*256 + p*256 + c
    if (idx >= BATCH * NPOS * NCH) return;
    int c  = idx % NCH;
    int bp = idx / NCH;
    int p  = bp % NPOS;
    int b  = bp / NPOS;
    int i = p / 10;
    int j = p % 10;
    g_Gt[idx] = feat[(((b * NCH + c) * 64) + i * 7) * 64 + j * 7];
}

// One column-strip of NCOLS grid columns -> NCOLS-1 output columns.
// All 10*NCOLS loads are unconditional, front-batched (MLP ~40, const-imm
// offsets -> no ALU). Region-of-discard masking runs on the FMA pipe:
//   mh[i] in {-1,0}, mw[k] in {1,0}; t = mh*mw; v = fmaf(v, t, v)
//   -> inside: v - v = +0 exactly; outside: v unchanged.
template<int NCOLS>
__device__ __forceinline__ void strip(const float* __restrict__ gt,
                                      float* __restrict__ so,
                                      float x1, float x2, float y1, float y2,
                                      int c0)
{
    float mw[NCOLS];
    #pragma unroll
    for (int k = 0; k < NCOLS; k++) {
        float w = (float)(c0 + k) * 7.0f;
        mw[k] = ((w >= x1) && (w <= x2)) ? 1.0f : 0.0f;
    }
    float mh[10];
    #pragma unroll
    for (int i = 0; i < 10; i++) {
        float h = (float)i * 7.0f;
        mh[i] = ((h >= y1) && (h <= y2)) ? -1.0f : 0.0f;
    }

    // Phase 1: front-batched unconditional loads of the whole window.
    float v[10][NCOLS];
    #pragma unroll
    for (int i = 0; i < 10; i++)
        #pragma unroll
        for (int k = 0; k < NCOLS; k++)
            v[i][k] = __ldg(&gt[(i * 10 + k) * NCH]);

    // Phase 2: multiplicative masking on the FMA pipe.
    #pragma unroll
    for (int i = 0; i < 10; i++)
        #pragma unroll
        for (int k = 0; k < NCOLS; k++) {
            float t = mh[i] * mw[k];
            v[i][k] = fmaf(v[i][k], t, v[i][k]);
        }

    // Phase 3: horizontal max first (rolling 2-row window), then vertical.
    float hp[NCOLS - 1], hc[NCOLS - 1];
    #pragma unroll
    for (int k = 0; k < NCOLS - 1; k++)
        hp[k] = fmaxf(v[0][k], v[0][k + 1]);
    #pragma unroll
    for (int i = 1; i < 10; i++) {
        #pragma unroll
        for (int k = 0; k < NCOLS - 1; k++)
            hc[k] = fmaxf(v[i][k], v[i][k + 1]);
        #pragma unroll
        for (int k = 0; k < NCOLS - 1; k++)
            so[(i - 1) * 9 + k] = fmaxf(hp[k], hc[k]);
        #pragma unroll
        for (int k = 0; k < NCOLS - 1; k++)
            hp[k] = hc[k];
    }
}

__global__ __launch_bounds__(THREADS, 4) void rod_align_max_kernel(
    const float* __restrict__ rois,
    float* __restrict__ out)
{
    __shared__ __align__(16) float sout[CHB * 81];   // 20736 B staged outputs

    const int r     = blockIdx.x;      // roi
    const int chunk = blockIdx.y;      // channel chunk
    const int tid   = threadIdx.x;
    // 4 column-strips; within each strip, warps hold 32 consecutive channels.
    //   q=0: cols 0..3 -> j=0..2     q=1: cols 3..5 -> j=3..4
    //   q=2: cols 5..7 -> j=5..6     q=3: cols 7..9 -> j=7..8
    const int c = tid & (CHB - 1);     // channel within chunk
    const int q = tid >> 6;            // strip id

    const float x1 = rois[r * 5 + 1] * 0.25f;
    const float y1 = rois[r * 5 + 2] * 0.25f;
    const float x2 = rois[r * 5 + 3] * 0.25f;
    const float y2 = rois[r * 5 + 4] * 0.25f;
    const int   b  = (int)rois[r * 5 + 0];

    const float* gbase = g_Gt + b * (NPOS * NCH) + chunk * CHB + c;
    float* so = sout + c * 81;

    if (q == 0)      strip<4>(gbase,           so,     x1, x2, y1, y2, 0);
    else if (q == 1) strip<3>(gbase + 3 * NCH, so + 3, x1, x2, y1, y2, 3);
    else if (q == 2) strip<3>(gbase + 5 * NCH, so + 5, x1, x2, y1, y2, 5);
    else             strip<3>(gbase + 7 * NCH, so + 7, x1, x2, y1, y2, 7);

    // Hand the 20736B contiguous staged block to TMA for the global write.
    asm volatile("fence.proxy.async.shared::cta;" ::: "memory");
    __syncthreads();
    if (tid == 0) {
        uint32_t saddr;
        asm("{ .reg .u64 t; cvta.to.shared.u64 t, %1; cvt.u32.u64 %0, t; }"
            : "=r"(saddr) : "l"(sout));
        float* gdst = out + (size_t)(r * NCH + chunk * CHB) * 81;
        asm volatile(
            "cp.async.bulk.global.shared::cta.bulk_group [%0], [%1], %2;"
            :: "l"(gdst), "r"(saddr), "r"((int)(CHB * 81 * 4)) : "memory");
        asm volatile("cp.async.bulk.commit_group;" ::: "memory");
        // Must not exit the CTA while TMA is still reading our smem.
        asm volatile("cp.async.bulk.wait_group.read 0;" ::: "memory");
    }
}

extern "C" void kernel_launch(void* const* d_in, const int* in_sizes, int n_in,
                              void* d_out, int out_size) {
    const float* features = (const float*)d_in[0];   // [4,256,64,64]
    const float* rois     = (const float*)d_in[1];   // [2048,5]
    float* out = (float*)d_out;                      // [2048,256,9,9]

    const int R = in_sizes[1] / 5;                   // 2048

    int n_g = BATCH * NPOS * NCH;
    gather_grid_kernel<<<(n_g + 255) / 256, 256>>>(features);

    dim3 grid(R, NCHUNK);
    rod_align_max_kernel<<<grid, THREADS>>>(rois, out);
}

// round 11
// speedup vs baseline: 1.4243x; 1.0009x over previous
#include <cuda_runtime.h>
#include <cstdint>

// Problem constants:
//   features: [B=4, C=256, H=64, W=64] fp32
//   rois:     [R=2048, 5] (batch, x1, y1, x2, y2), SPATIAL_SCALE = 0.25
//   Grid positions h=w={0,7,...,63} are EXACT integers -> bilinear == gather.
//   output:   [R, C, 9, 9] fp32  (maxpool 2x2 s1 of region-of-discard-masked 10x10)

#define BATCH 4
#define NCH   256
#define NPOS  100        // 10x10 grid per channel
#define CHB   64         // channels per block
#define NCHUNK (NCH / CHB)
#define THREADS 256      // 64 channels x 4 column-strips

// Transposed gather: G_t[b][pos][c] = features[b,c,7i,7j], channels contiguous.
__device__ float g_Gt[BATCH * NPOS * NCH];

__global__ void gather_grid_kernel(const float* __restrict__ feat) {
    int idx = blockIdx.x * blockDim.x + threadIdx.x;   // b*100*256 + p*256 + c
    if (idx >= BATCH * NPOS * NCH) return;
    int c  = idx % NCH;
    int bp = idx / NCH;
    int p  = bp % NPOS;
    int b  = bp / NPOS;
    int i = p / 10;
    int j = p % 10;
    g_Gt[idx] = feat[(((b * NCH + c) * 64) + i * 7) * 64 + j * 7];
}

// One column-strip of NCOLS grid columns -> NCOLS-1 output columns.
// Two 5-row phases; each phase front-batches 5*NCOLS unconditional LDGs
// (MLP~20) then masks on the FMA pipe:
//   mw[k] in {-1,0}, mh in {1,0}; v = fmaf(v, mh*mw, v)
//   -> inside: v - v = +0 exactly; outside: v unchanged.
// Live window is 5*NCOLS floats -> regs ~45 -> 5+ CTAs/SM.
template<int NCOLS>
__device__ __forceinline__ void strip(const float* __restrict__ gt,
                                      float* __restrict__ so,
                                      float x1, float x2, float y1, float y2,
                                      int c0)
{
    float mw[NCOLS];
    #pragma unroll
    for (int k = 0; k < NCOLS; k++) {
        float w = (float)(c0 + k) * 7.0f;
        mw[k] = ((w >= x1) && (w <= x2)) ? -1.0f : 0.0f;
    }

    float v[5][NCOLS];
    float hp[NCOLS - 1];

    // ---- Phase A: rows 0..4 -> output rows 0..3 ----
    #pragma unroll
    for (int i = 0; i < 5; i++)
        #pragma unroll
        for (int k = 0; k < NCOLS; k++)
            v[i][k] = __ldg(&gt[(i * 10 + k) * NCH]);

    #pragma unroll
    for (int i = 0; i < 5; i++) {
        float h = (float)i * 7.0f;
        float mh = ((h >= y1) && (h <= y2)) ? 1.0f : 0.0f;
        #pragma unroll
        for (int k = 0; k < NCOLS; k++)
            v[i][k] = fmaf(v[i][k], mh * mw[k], v[i][k]);
    }

    #pragma unroll
    for (int k = 0; k < NCOLS - 1; k++)
        hp[k] = fmaxf(v[0][k], v[0][k + 1]);
    #pragma unroll
    for (int i = 1; i < 5; i++) {
        float hc[NCOLS - 1];
        #pragma unroll
        for (int k = 0; k < NCOLS - 1; k++)
            hc[k] = fmaxf(v[i][k], v[i][k + 1]);
        #pragma unroll
        for (int k = 0; k < NCOLS - 1; k++)
            so[(i - 1) * 9 + k] = fmaxf(hp[k], hc[k]);
        #pragma unroll
        for (int k = 0; k < NCOLS - 1; k++)
            hp[k] = hc[k];
    }

    // ---- Phase B: rows 5..9 -> output rows 4..8 (hp carries row 4) ----
    #pragma unroll
    for (int i = 0; i < 5; i++)
        #pragma unroll
        for (int k = 0; k < NCOLS; k++)
            v[i][k] = __ldg(&gt[((i + 5) * 10 + k) * NCH]);

    #pragma unroll
    for (int i = 0; i < 5; i++) {
        float h = (float)(i + 5) * 7.0f;
        float mh = ((h >= y1) && (h <= y2)) ? 1.0f : 0.0f;
        #pragma unroll
        for (int k = 0; k < NCOLS; k++)
            v[i][k] = fmaf(v[i][k], mh * mw[k], v[i][k]);
    }

    #pragma unroll
    for (int i = 0; i < 5; i++) {
        float hc[NCOLS - 1];
        #pragma unroll
        for (int k = 0; k < NCOLS - 1; k++)
            hc[k] = fmaxf(v[i][k], v[i][k + 1]);
        #pragma unroll
        for (int k = 0; k < NCOLS - 1; k++)
            so[(i + 4) * 9 + k] = fmaxf(hp[k], hc[k]);
        #pragma unroll
        for (int k = 0; k < NCOLS - 1; k++)
            hp[k] = hc[k];
    }
}

__global__ __launch_bounds__(THREADS, 5) void rod_align_max_kernel(
    const float* __restrict__ rois,
    float* __restrict__ out)
{
    __shared__ __align__(16) float sout[CHB * 81];   // 20736 B staged outputs

    const int r     = blockIdx.x;      // roi
    const int chunk = blockIdx.y;      // channel chunk
    const int tid   = threadIdx.x;
    // 4 column-strips; within each strip, warps hold 32 consecutive channels.
    //   q=0: cols 0..3 -> j=0..2     q=1: cols 3..5 -> j=3..4
    //   q=2: cols 5..7 -> j=5..6     q=3: cols 7..9 -> j=7..8
    const int c = tid & (CHB - 1);     // channel within chunk
    const int q = tid >> 6;            // strip id

    const float x1 = rois[r * 5 + 1] * 0.25f;
    const float y1 = rois[r * 5 + 2] * 0.25f;
    const float x2 = rois[r * 5 + 3] * 0.25f;
    const float y2 = rois[r * 5 + 4] * 0.25f;
    const int   b  = (int)rois[r * 5 + 0];

    const float* gbase = g_Gt + b * (NPOS * NCH) + chunk * CHB + c;
    float* so = sout + c * 81;

    if (q == 0)      strip<4>(gbase,           so,     x1, x2, y1, y2, 0);
    else if (q == 1) strip<3>(gbase + 3 * NCH, so + 3, x1, x2, y1, y2, 3);
    else if (q == 2) strip<3>(gbase + 5 * NCH, so + 5, x1, x2, y1, y2, 5);
    else             strip<3>(gbase + 7 * NCH, so + 7, x1, x2, y1, y2, 7);

    // Hand the 20736B contiguous staged block to TMA for the global write.
    asm volatile("fence.proxy.async.shared::cta;" ::: "memory");
    __syncthreads();
    if (tid == 0) {
        uint32_t saddr;
        asm("{ .reg .u64 t; cvta.to.shared.u64 t, %1; cvt.u32.u64 %0, t; }"
            : "=r"(saddr) : "l"(sout));
        float* gdst = out + (size_t)(r * NCH + chunk * CHB) * 81;
        asm volatile(
            "cp.async.bulk.global.shared::cta.bulk_group [%0], [%1], %2;"
            :: "l"(gdst), "r"(saddr), "r"((int)(CHB * 81 * 4)) : "memory");
        asm volatile("cp.async.bulk.commit_group;" ::: "memory");
        // Must not exit the CTA while TMA is still reading our smem.
        asm volatile("cp.async.bulk.wait_group.read 0;" ::: "memory");
    }
}

extern "C" void kernel_launch(void* const* d_in, const int* in_sizes, int n_in,
                              void* d_out, int out_size) {
    const float* features = (const float*)d_in[0];   // [4,256,64,64]
    const float* rois     = (const float*)d_in[1];   // [2048,5]
    float* out = (float*)d_out;                      // [2048,256,9,9]

    const int R = in_sizes[1] / 5;                   // 2048

    int n_g = BATCH * NPOS * NCH;
    gather_grid_kernel<<<(n_g + 255) / 256, 256>>>(features);

    dim3 grid(R, NCHUNK);
    rod_align_max_kernel<<<grid, THREADS>>>(rois, out);
}

// round 12
// speedup vs baseline: 1.4426x; 1.0129x over previous
#include <cuda_runtime.h>
#include <cstdint>

// Problem constants:
//   features: [B=4, C=256, H=64, W=64] fp32
//   rois:     [R=2048, 5] (batch, x1, y1, x2, y2), SPATIAL_SCALE = 0.25
//   Grid positions h=w={0,7,...,63} are EXACT integers -> bilinear == gather.
//   output:   [R, C, 9, 9] fp32  (maxpool 2x2 s1 of region-of-discard-masked 10x10)

#define BATCH 4
#define NCH   256
#define NPOS  100        // 10x10 grid per channel
#define CHB   64         // channels per block
#define NCHUNK (NCH / CHB)
#define THREADS 256      // 64 channels x 4 column-strips

// Transposed gather: G_t[b][pos][c] = features[b,c,7i,7j], channels contiguous.
__device__ float g_Gt[BATCH * NPOS * NCH];

__global__ void gather_grid_kernel(const float* __restrict__ feat) {
    int idx = blockIdx.x * blockDim.x + threadIdx.x;   // b*100*256 + p*256 + c
    if (idx >= BATCH * NPOS * NCH) return;
    int c  = idx % NCH;
    int bp = idx / NCH;
    int p  = bp % NPOS;
    int b  = bp / NPOS;
    int i = p / 10;
    int j = p % 10;
    g_Gt[idx] = feat[(((b * NCH + c) * 64) + i * 7) * 64 + j * 7];
}

// One column-strip of NCOLS grid columns -> NCOLS-1 output columns.
// Two 5-row phases; each phase front-batches 5*NCOLS unconditional LDGs
// (MLP~20) then masks on the FMA pipe:
//   mw[k] in {-1,0}, mh in {1,0}; v = fmaf(v, mh*mw, v)
//   -> inside: v - v = +0 exactly; outside: v unchanged.
// Live window is 5*NCOLS floats -> regs ~45 -> 5+ CTAs/SM.
template<int NCOLS>
__device__ __forceinline__ void strip(const float* __restrict__ gt,
                                      float* __restrict__ so,
                                      float x1, float x2, float y1, float y2,
                                      int c0)
{
    float mw[NCOLS];
    #pragma unroll
    for (int k = 0; k < NCOLS; k++) {
        float w = (float)(c0 + k) * 7.0f;
        mw[k] = ((w >= x1) && (w <= x2)) ? -1.0f : 0.0f;
    }

    float v[5][NCOLS];
    float hp[NCOLS - 1];

    // ---- Phase A: rows 0..4 -> output rows 0..3 ----
    #pragma unroll
    for (int i = 0; i < 5; i++)
        #pragma unroll
        for (int k = 0; k < NCOLS; k++)
            v[i][k] = __ldg(&gt[(i * 10 + k) * NCH]);

    #pragma unroll
    for (int i = 0; i < 5; i++) {
        float h = (float)i * 7.0f;
        float mh = ((h >= y1) && (h <= y2)) ? 1.0f : 0.0f;
        #pragma unroll
        for (int k = 0; k < NCOLS; k++)
            v[i][k] = fmaf(v[i][k], mh * mw[k], v[i][k]);
    }

    #pragma unroll
    for (int k = 0; k < NCOLS - 1; k++)
        hp[k] = fmaxf(v[0][k], v[0][k + 1]);
    #pragma unroll
    for (int i = 1; i < 5; i++) {
        float hc[NCOLS - 1];
        #pragma unroll
        for (int k = 0; k < NCOLS - 1; k++)
            hc[k] = fmaxf(v[i][k], v[i][k + 1]);
        #pragma unroll
        for (int k = 0; k < NCOLS - 1; k++)
            so[(i - 1) * 9 + k] = fmaxf(hp[k], hc[k]);
        #pragma unroll
        for (int k = 0; k < NCOLS - 1; k++)
            hp[k] = hc[k];
    }

    // ---- Phase B: rows 5..9 -> output rows 4..8 (hp carries row 4) ----
    #pragma unroll
    for (int i = 0; i < 5; i++)
        #pragma unroll
        for (int k = 0; k < NCOLS; k++)
            v[i][k] = __ldg(&gt[((i + 5) * 10 + k) * NCH]);

    #pragma unroll
    for (int i = 0; i < 5; i++) {
        float h = (float)(i + 5) * 7.0f;
        float mh = ((h >= y1) && (h <= y2)) ? 1.0f : 0.0f;
        #pragma unroll
        for (int k = 0; k < NCOLS; k++)
            v[i][k] = fmaf(v[i][k], mh * mw[k], v[i][k]);
    }

    #pragma unroll
    for (int i = 0; i < 5; i++) {
        float hc[NCOLS - 1];
        #pragma unroll
        for (int k = 0; k < NCOLS - 1; k++)
            hc[k] = fmaxf(v[i][k], v[i][k + 1]);
        #pragma unroll
        for (int k = 0; k < NCOLS - 1; k++)
            so[(i + 4) * 9 + k] = fmaxf(hp[k], hc[k]);
        #pragma unroll
        for (int k = 0; k < NCOLS - 1; k++)
            hp[k] = hc[k];
    }
}

__global__ __launch_bounds__(THREADS, 5) void rod_align_max_kernel(
    const float* __restrict__ rois,
    float* __restrict__ out)
{
    __shared__ __align__(16) float sout[CHB * 81];   // 20736 B staged outputs

    const int r     = blockIdx.x;      // roi
    const int chunk = blockIdx.y;      // channel chunk
    const int tid   = threadIdx.x;
    // 4 column-strips; within each strip, warps hold 32 consecutive channels.
    //   q=0: cols 0..3 -> j=0..2     q=1: cols 3..5 -> j=3..4
    //   q=2: cols 5..7 -> j=5..6     q=3: cols 7..9 -> j=7..8
    const int c = tid & (CHB - 1);     // channel within chunk
    const int q = tid >> 6;            // strip id

    const float x1 = rois[r * 5 + 1] * 0.25f;
    const float y1 = rois[r * 5 + 2] * 0.25f;
    const float x2 = rois[r * 5 + 3] * 0.25f;
    const float y2 = rois[r * 5 + 4] * 0.25f;
    const int   b  = (int)rois[r * 5 + 0];

    const float* gbase = g_Gt + b * (NPOS * NCH) + chunk * CHB + c;
    float* so = sout + c * 81;

    if (q == 0)      strip<4>(gbase,           so,     x1, x2, y1, y2, 0);
    else if (q == 1) strip<3>(gbase + 3 * NCH, so + 3, x1, x2, y1, y2, 3);
    else if (q == 2) strip<3>(gbase + 5 * NCH, so + 5, x1, x2, y1, y2, 5);
    else             strip<3>(gbase + 7 * NCH, so + 7, x1, x2, y1, y2, 7);

    // Hand the 20736B contiguous staged block to TMA for the global write.
    asm volatile("fence.proxy.async.shared::cta;" ::: "memory");
    __syncthreads();
    if (tid == 0) {
        uint32_t saddr;
        asm("{ .reg .u64 t; cvta.to.shared.u64 t, %1; cvt.u32.u64 %0, t; }"
            : "=r"(saddr) : "l"(sout));
        float* gdst = out + (size_t)(r * NCH + chunk * CHB) * 81;
        asm volatile(
            "cp.async.bulk.global.shared::cta.bulk_group [%0], [%1], %2;"
            :: "l"(gdst), "r"(saddr), "r"((int)(CHB * 81 * 4)) : "memory");
        asm volatile("cp.async.bulk.commit_group;" ::: "memory");
        // Must not exit the CTA while TMA is still reading our smem.
        asm volatile("cp.async.bulk.wait_group.read 0;" ::: "memory");
    }
}

extern "C" void kernel_launch(void* const* d_in, const int* in_sizes, int n_in,
                              void* d_out, int out_size) {
    const float* features = (const float*)d_in[0];   // [4,256,64,64]
    const float* rois     = (const float*)d_in[1];   // [2048,5]
    float* out = (float*)d_out;                      // [2048,256,9,9]

    const int R = in_sizes[1] / 5;                   // 2048

    int n_g = BATCH * NPOS * NCH;
    gather_grid_kernel<<<(n_g + 255) / 256, 256>>>(features);

    dim3 grid(R, NCHUNK);
    rod_align_max_kernel<<<grid, THREADS>>>(rois, out);
}